// round 14
// baseline (speedup 1.0000x reference)
#include <cuda_runtime.h>
#include <cuda.h>
#include <cstdint>

#define NUM_EXPERTS 16
#define DIM 1024
#define THREADS 288            // 8 compute warps + 1 producer warp
#define GRID 148
#define TILE_TOK 64
#define KC 32                  // dims per chunk
#define NCH 32                 // chunks per tile
#define NSTAGE 6
#define STAGE_B 8192           // 64 tok x 32 dims x 4B, SW128

// smem layout (bytes)
#define WF_OFF   0             // 128KB packed W fragments (hi/lo tf32)
#define X_OFF    131072        // 6 x 8KB stages
#define SCR_OFF  (X_OFF + NSTAGE * STAGE_B)      // 180224
#define SCR_BUF  20480                           // 4 ksplit x 64 tok x 80B
#define BIAS_OFF (SCR_OFF + 2 * SCR_BUF)         // 221184
#define MB_OFF   (BIAS_OFF + 64)                 // full[6]@0, empty[6]@48
#define SMEM_BYTES (MB_OFF + 96 + 32)

__device__ __forceinline__ void mbar_init(uint32_t bar, uint32_t cnt) {
    asm volatile("mbarrier.init.shared.b64 [%0], %1;" :: "r"(bar), "r"(cnt) : "memory");
}
__device__ __forceinline__ void mbar_expect_tx(uint32_t bar, uint32_t bytes) {
    asm volatile("mbarrier.arrive.expect_tx.shared.b64 _, [%0], %1;"
                 :: "r"(bar), "r"(bytes) : "memory");
}
__device__ __forceinline__ void mbar_arrive(uint32_t bar) {
    asm volatile("mbarrier.arrive.shared.b64 _, [%0];" :: "r"(bar) : "memory");
}
__device__ __forceinline__ void mbar_wait(uint32_t bar, uint32_t parity) {
    uint32_t done;
    asm volatile(
        "{\n\t.reg .pred p;\n\t"
        "mbarrier.try_wait.parity.acquire.cta.shared::cta.b64 p, [%1], %2;\n\t"
        "selp.b32 %0, 1, 0, p;\n\t}"
        : "=r"(done) : "r"(bar), "r"(parity) : "memory");
    if (!done) {
        asm volatile(
            "{\n\t.reg .pred P1;\n\t"
            "WL_%=:\n\t"
            "mbarrier.try_wait.parity.acquire.cta.shared::cta.b64 P1, [%0], %1, 0x989680;\n\t"
            "@P1 bra.uni WD_%=;\n\t"
            "bra.uni WL_%=;\n\t"
            "WD_%=:\n\t}"
            :: "r"(bar), "r"(parity) : "memory");
    }
}

__device__ __forceinline__ void mma_tf32(float* d, const uint32_t* a, const uint32_t* bf) {
    asm volatile(
        "mma.sync.aligned.m16n8k8.row.col.f32.tf32.tf32.f32 "
        "{%0,%1,%2,%3}, {%4,%5,%6,%7}, {%8,%9}, {%0,%1,%2,%3};"
        : "+f"(d[0]), "+f"(d[1]), "+f"(d[2]), "+f"(d[3])
        : "r"(a[0]), "r"(a[1]), "r"(a[2]), "r"(a[3]), "r"(bf[0]), "r"(bf[1]));
}

__global__ __launch_bounds__(THREADS, 1)
void gating_kernel(const float* __restrict__ W,
                   const float* __restrict__ b,
                   float* __restrict__ out,
                   int T,
                   const __grid_constant__ CUtensorMap tmap) {
    extern __shared__ char smem[];
    const uint32_t su = (uint32_t)__cvta_generic_to_shared(smem);
    const int tid  = threadIdx.x;
    const int wid  = tid >> 5;
    const int lane = tid & 31;
    const int NT   = T / TILE_TOK;                       // 1024 tiles
    const int bid  = blockIdx.x;
    const int ntl  = (NT - bid + GRID - 1) / GRID;       // tiles for this CTA
    const int G    = ntl * NCH;

    const uint32_t fullb  = su + MB_OFF;
    const uint32_t emptyb = su + MB_OFF + 48;

    if (tid == 0) {
#pragma unroll
        for (int i = 0; i < NSTAGE; i++) {
            mbar_init(fullb + i * 8, 1);
            mbar_init(emptyb + i * 8, 8);
        }
    }

    // Pack W fragments: byte = (((k2*2+hl)*2+nt)*2+reg)*128 + lane*4
    // value = (hl ? lo : hi) of W[e][d], e = nt*8 + (l>>2), d = k2*8 + (l&3) + reg*4
    for (int i = tid; i < 32768; i += THREADS) {
        int l = i & 31, reg = (i >> 5) & 1, nt = (i >> 6) & 1, hl = (i >> 7) & 1, k2 = i >> 8;
        int e = nt * 8 + (l >> 2);
        int d = k2 * 8 + (l & 3) + reg * 4;
        float w = W[(e << 10) | d];
        uint32_t hb; asm("cvt.rna.tf32.f32 %0, %1;" : "=r"(hb) : "f"(w));
        float hf = __uint_as_float(hb);
        float v = hl ? (w - hf) : hf;
        *reinterpret_cast<float*>(smem + WF_OFF + (size_t)i * 4) = v;
    }
    if (tid < NUM_EXPERTS)
        *reinterpret_cast<float*>(smem + BIAS_OFF + tid * 4) = b[tid];
    asm volatile("fence.proxy.async.shared::cta;" ::: "memory");
    __syncthreads();

    if (wid == 8) {
        // ---- TMA producer warp ----
        int s = 0, ep = 1, c = 0, ti = 0;
        for (int g = 0; g < G; g++) {
            if (g >= NSTAGE) mbar_wait(emptyb + s * 8, (uint32_t)ep);
            if (lane == 0) {
                mbar_expect_tx(fullb + s * 8, STAGE_B);
                int tok = (bid + ti * GRID) * TILE_TOK;
                asm volatile(
                    "cp.async.bulk.tensor.2d.shared::cta.global.tile.mbarrier::complete_tx::bytes "
                    "[%0], [%1, {%2, %3}], [%4];"
                    :: "r"(su + X_OFF + s * STAGE_B), "l"(&tmap),
                       "r"(c * KC), "r"(tok), "r"(fullb + s * 8) : "memory");
            }
            if (++s == NSTAGE) { s = 0; ep ^= 1; }
            if (++c == NCH) { c = 0; ti++; }
        }
        return;
    }

    // ---- compute warps: wid = (q<<2) | ks ----
    const int q  = wid >> 2;          // token half (32 tokens)
    const int ks = wid & 3;           // K split (8 dims of each 32-dim chunk)
    const uint32_t swz  = (uint32_t)(lane >> 2) << 4;
    const uint32_t d4   = (uint32_t)(ks * 32 + (lane & 3) * 4);
    const uint32_t rowb = (uint32_t)(lane >> 2) * 128 + (uint32_t)q * 4096;
    const uint32_t rA0  = rowb + (d4 ^ swz);
    const uint32_t rA1  = rowb + ((d4 + 16) ^ swz);
    const uint32_t wfl  = su + WF_OFF + (uint32_t)ks * 1024 + (uint32_t)lane * 4;
    const float* b_s = reinterpret_cast<const float*>(smem + BIAS_OFF);

    float acc[16];                    // [m][nt][4]
#pragma unroll
    for (int i = 0; i < 16; i++) acc[i] = 0.0f;

    int s = 0, fp = 0, c = 0, tb = 0;
    for (int g = 0; g < G; g++) {
        mbar_wait(fullb + s * 8, (uint32_t)fp);

        const uint32_t aA = su + X_OFF + (uint32_t)s * STAGE_B + rA0;
        const uint32_t aB = su + X_OFF + (uint32_t)s * STAGE_B + rA1;
        uint32_t a[8];
        asm volatile("ld.shared.b32 %0, [%1];"           : "=r"(a[0]) : "r"(aA));
        asm volatile("ld.shared.b32 %0, [%1+1024];"      : "=r"(a[1]) : "r"(aA));
        asm volatile("ld.shared.b32 %0, [%1];"           : "=r"(a[2]) : "r"(aB));
        asm volatile("ld.shared.b32 %0, [%1+1024];"      : "=r"(a[3]) : "r"(aB));
        asm volatile("ld.shared.b32 %0, [%1+2048];"      : "=r"(a[4]) : "r"(aA));
        asm volatile("ld.shared.b32 %0, [%1+3072];"      : "=r"(a[5]) : "r"(aA));
        asm volatile("ld.shared.b32 %0, [%1+2048];"      : "=r"(a[6]) : "r"(aB));
        asm volatile("ld.shared.b32 %0, [%1+3072];"      : "=r"(a[7]) : "r"(aB));
        if (lane == 0) mbar_arrive(emptyb + s * 8);

        // Split x = hi(tf32) + lo; feed lo raw (HW truncation adds only ~2^-22)
        uint32_t al[8];
#pragma unroll
        for (int i = 0; i < 8; i++) {
            float av = __uint_as_float(a[i]);
            uint32_t hb;
            asm("cvt.rna.tf32.f32 %0, %1;" : "=r"(hb) : "f"(av));
            al[i] = __float_as_uint(av - __uint_as_float(hb));
            a[i] = hb;
        }

        const uint32_t wb = wfl + (uint32_t)c * 4096;
        uint32_t bf[8];
        asm volatile("ld.shared.b32 %0, [%1];"      : "=r"(bf[0]) : "r"(wb));
        asm volatile("ld.shared.b32 %0, [%1+128];"  : "=r"(bf[1]) : "r"(wb));
        asm volatile("ld.shared.b32 %0, [%1+256];"  : "=r"(bf[2]) : "r"(wb));
        asm volatile("ld.shared.b32 %0, [%1+384];"  : "=r"(bf[3]) : "r"(wb));
        asm volatile("ld.shared.b32 %0, [%1+512];"  : "=r"(bf[4]) : "r"(wb));
        asm volatile("ld.shared.b32 %0, [%1+640];"  : "=r"(bf[5]) : "r"(wb));
        asm volatile("ld.shared.b32 %0, [%1+768];"  : "=r"(bf[6]) : "r"(wb));
        asm volatile("ld.shared.b32 %0, [%1+896];"  : "=r"(bf[7]) : "r"(wb));

        // term 1: xh * Wh (4 independent accumulators -> ILP)
        mma_tf32(acc + 0,  a + 0, bf + 0);
        mma_tf32(acc + 4,  a + 0, bf + 2);
        mma_tf32(acc + 8,  a + 4, bf + 0);
        mma_tf32(acc + 12, a + 4, bf + 2);
        // term 2: xh * Wl
        mma_tf32(acc + 0,  a + 0, bf + 4);
        mma_tf32(acc + 4,  a + 0, bf + 6);
        mma_tf32(acc + 8,  a + 4, bf + 4);
        mma_tf32(acc + 12, a + 4, bf + 6);
        // term 3: xl * Wh
        mma_tf32(acc + 0,  al + 0, bf + 0);
        mma_tf32(acc + 4,  al + 0, bf + 2);
        mma_tf32(acc + 8,  al + 4, bf + 0);
        mma_tf32(acc + 12, al + 4, bf + 2);

        if (++s == NSTAGE) { s = 0; fp ^= 1; }
        if (++c == NCH) {
            c = 0;
            // ---- per-tile epilogue ----
            const int buf = tb & 1;
            const uint32_t scr = su + SCR_OFF + (uint32_t)buf * SCR_BUF + (uint32_t)ks * 5120;
#pragma unroll
            for (int m = 0; m < 2; m++) {
#pragma unroll
                for (int nt = 0; nt < 2; nt++) {
                    int tokr = q * 32 + m * 16 + (lane >> 2);
                    uint32_t ad = scr + (uint32_t)tokr * 80
                                + (uint32_t)(nt * 8 + (lane & 3) * 2) * 4;
                    const float* A4 = acc + (m * 2 + nt) * 4;
                    asm volatile("st.shared.v2.f32 [%0], {%1, %2};"
                                 :: "r"(ad), "f"(A4[0]), "f"(A4[1]) : "memory");
                    asm volatile("st.shared.v2.f32 [%0+640], {%1, %2};"
                                 :: "r"(ad), "f"(A4[2]), "f"(A4[3]) : "memory");
                }
            }
            asm volatile("bar.sync 1, 256;" ::: "memory");

            if (tid < 64) {
                const uint32_t sb = su + SCR_OFF + (uint32_t)buf * SCR_BUF + (uint32_t)tid * 80;
                float lg[16];
#pragma unroll
                for (int i = 0; i < 16; i++) lg[i] = b_s[i];
#pragma unroll
                for (int s4 = 0; s4 < 4; s4++) {
#pragma unroll
                    for (int qd = 0; qd < 4; qd++) {
                        float v0, v1, v2, v3;
                        asm volatile("ld.shared.v4.f32 {%0, %1, %2, %3}, [%4];"
                                     : "=f"(v0), "=f"(v1), "=f"(v2), "=f"(v3)
                                     : "r"(sb + (uint32_t)(s4 * 5120 + qd * 16)));
                        lg[qd * 4 + 0] += v0; lg[qd * 4 + 1] += v1;
                        lg[qd * 4 + 2] += v2; lg[qd * 4 + 3] += v3;
                    }
                }
                float m = lg[0];
#pragma unroll
                for (int e = 1; e < NUM_EXPERTS; e++) m = fmaxf(m, lg[e]);
                float sum = 0.0f;
#pragma unroll
                for (int e = 0; e < NUM_EXPERTS; e++) {
                    float w = __expf(lg[e] - m);
                    lg[e] = w;
                    sum += w;
                }
                const float inv = __fdividef(1.0f, sum);
#pragma unroll
                for (int e = 0; e < NUM_EXPERTS; e++) lg[e] *= inv;

                float v1 = -1.0f, v2 = -1.0f;
                int i1 = 0, i2 = 0;
#pragma unroll
                for (int e = 0; e < NUM_EXPERTS; e++) {
                    float w = lg[e];
                    if (w > v1) { v2 = v1; i2 = i1; v1 = w; i1 = e; }
                    else if (w > v2) { v2 = w; i2 = e; }
                }
                const size_t t = (size_t)(bid + tb * GRID) * TILE_TOK + tid;
                float* outg = out;
                float* outw = out + (size_t)NUM_EXPERTS * T;
#pragma unroll
                for (int e = 0; e < NUM_EXPERTS; e++) {
                    float gg = (e == i1) ? v1 : ((e == i2) ? v2 : 0.0f);
                    outg[(size_t)e * T + t] = gg;
                    outw[(size_t)e * T + t] = lg[e];
                }
            }
#pragma unroll
            for (int i = 0; i < 16; i++) acc[i] = 0.0f;
            tb++;
        }
    }
}

typedef CUresult (*PFN_encodeTiled)(
    CUtensorMap*, CUtensorMapDataType, cuuint32_t, void*,
    const cuuint64_t*, const cuuint64_t*, const cuuint32_t*, const cuuint32_t*,
    CUtensorMapInterleave, CUtensorMapSwizzle, CUtensorMapL2promotion,
    CUtensorMapFloatOOBfill);

extern "C" void kernel_launch(void* const* d_in, const int* in_sizes, int n_in,
                              void* d_out, int out_size) {
    const float* x = (const float*)d_in[0];
    const float* W = (const float*)d_in[1];
    const float* b = (const float*)d_in[2];
    float* out = (float*)d_out;
    const int T = in_sizes[0] / DIM;           // 65536 tokens

    static PFN_encodeTiled encode_fn = nullptr;
    if (!encode_fn) {
        void* fp = nullptr;
        cudaDriverEntryPointQueryResult st;
        cudaGetDriverEntryPoint("cuTensorMapEncodeTiled", &fp,
                                cudaEnableDefault, &st);
        encode_fn = (PFN_encodeTiled)fp;
    }

    CUtensorMap tmap;
    {
        cuuint64_t gdims[2]    = {(cuuint64_t)DIM, (cuuint64_t)T};
        cuuint64_t gstrides[1] = {(cuuint64_t)DIM * 4};
        cuuint32_t box[2]      = {KC, TILE_TOK};
        cuuint32_t estr[2]     = {1, 1};
        encode_fn(&tmap, CU_TENSOR_MAP_DATA_TYPE_FLOAT32, 2, (void*)x,
                  gdims, gstrides, box, estr,
                  CU_TENSOR_MAP_INTERLEAVE_NONE, CU_TENSOR_MAP_SWIZZLE_128B,
                  CU_TENSOR_MAP_L2_PROMOTION_L2_128B,
                  CU_TENSOR_MAP_FLOAT_OOB_FILL_NONE);
    }

    cudaFuncSetAttribute(gating_kernel,
                         cudaFuncAttributeMaxDynamicSharedMemorySize, SMEM_BYTES);
    gating_kernel<<<GRID, THREADS, SMEM_BYTES>>>(W, b, out, T, tmap);
}

// round 15
// speedup vs baseline: 1.0887x; 1.0887x over previous
#include <cuda_runtime.h>
#include <cuda.h>
#include <cstdint>

#define NUM_EXPERTS 16
#define DIM 1024
#define THREADS 544            // 16 compute warps + 1 producer warp
#define GRID 148
#define TILE_TOK 128
#define KC 32                  // dims per chunk
#define NCH 32                 // chunks per tile
#define NSTAGE 3
#define STAGE_B 16384          // 128 tok x 32 dims x 4B, SW128

// smem layout (bytes)
#define WF_OFF   0             // 128KB packed W fragments (hi/lo tf32)
#define X_OFF    131072        // 3 x 16KB stages
#define SCR_OFF  (X_OFF + NSTAGE * STAGE_B)      // 180224
#define SCR_KS   10240                           // 128 tok x 80B per ksplit
#define BIAS_OFF (SCR_OFF + 4 * SCR_KS)          // 221184
#define MB_OFF   (BIAS_OFF + 64)                 // full[3]@0, empty[3]@48
#define SMEM_BYTES (MB_OFF + 96 + 32)

__device__ __forceinline__ void mbar_init(uint32_t bar, uint32_t cnt) {
    asm volatile("mbarrier.init.shared.b64 [%0], %1;" :: "r"(bar), "r"(cnt) : "memory");
}
__device__ __forceinline__ void mbar_expect_tx(uint32_t bar, uint32_t bytes) {
    asm volatile("mbarrier.arrive.expect_tx.shared.b64 _, [%0], %1;"
                 :: "r"(bar), "r"(bytes) : "memory");
}
__device__ __forceinline__ void mbar_arrive(uint32_t bar) {
    asm volatile("mbarrier.arrive.shared.b64 _, [%0];" :: "r"(bar) : "memory");
}
__device__ __forceinline__ void mbar_wait(uint32_t bar, uint32_t parity) {
    uint32_t done;
    asm volatile(
        "{\n\t.reg .pred p;\n\t"
        "mbarrier.try_wait.parity.acquire.cta.shared::cta.b64 p, [%1], %2;\n\t"
        "selp.b32 %0, 1, 0, p;\n\t}"
        : "=r"(done) : "r"(bar), "r"(parity) : "memory");
    if (!done) {
        asm volatile(
            "{\n\t.reg .pred P1;\n\t"
            "WL_%=:\n\t"
            "mbarrier.try_wait.parity.acquire.cta.shared::cta.b64 P1, [%0], %1, 0x989680;\n\t"
            "@P1 bra.uni WD_%=;\n\t"
            "bra.uni WL_%=;\n\t"
            "WD_%=:\n\t}"
            :: "r"(bar), "r"(parity) : "memory");
    }
}

__device__ __forceinline__ void mma_tf32(float* d, const uint32_t* a, const uint32_t* bf) {
    asm volatile(
        "mma.sync.aligned.m16n8k8.row.col.f32.tf32.tf32.f32 "
        "{%0,%1,%2,%3}, {%4,%5,%6,%7}, {%8,%9}, {%0,%1,%2,%3};"
        : "+f"(d[0]), "+f"(d[1]), "+f"(d[2]), "+f"(d[3])
        : "r"(a[0]), "r"(a[1]), "r"(a[2]), "r"(a[3]), "r"(bf[0]), "r"(bf[1]));
}

__global__ __launch_bounds__(THREADS, 1)
void gating_kernel(const float* __restrict__ W,
                   const float* __restrict__ b,
                   float* __restrict__ out,
                   int T,
                   const __grid_constant__ CUtensorMap tmap) {
    extern __shared__ char smem[];
    const uint32_t su = (uint32_t)__cvta_generic_to_shared(smem);
    const int tid  = threadIdx.x;
    const int wid  = tid >> 5;
    const int lane = tid & 31;
    const int NT   = T / TILE_TOK;                       // 512 tiles
    const int bid  = blockIdx.x;
    const int ntl  = (NT - bid + GRID - 1) / GRID;       // tiles for this CTA
    const int G    = ntl * NCH;

    const uint32_t fullb  = su + MB_OFF;
    const uint32_t emptyb = su + MB_OFF + 48;

    if (tid == 0) {
#pragma unroll
        for (int i = 0; i < NSTAGE; i++) {
            mbar_init(fullb + i * 8, 1);
            mbar_init(emptyb + i * 8, 16);
        }
    }

    // Pack W fragments: byte = (((k2*2+hl)*2+nt)*2+reg)*128 + lane*4
    // value = (hl ? lo : hi) of W[e][d], e = nt*8 + (l>>2), d = k2*8 + (l&3) + reg*4
    for (int i = tid; i < 32768; i += THREADS) {
        int l = i & 31, reg = (i >> 5) & 1, nt = (i >> 6) & 1, hl = (i >> 7) & 1, k2 = i >> 8;
        int e = nt * 8 + (l >> 2);
        int d = k2 * 8 + (l & 3) + reg * 4;
        float w = W[(e << 10) | d];
        uint32_t hb; asm("cvt.rna.tf32.f32 %0, %1;" : "=r"(hb) : "f"(w));
        float hf = __uint_as_float(hb);
        float v = hl ? (w - hf) : hf;
        *reinterpret_cast<float*>(smem + WF_OFF + (size_t)i * 4) = v;
    }
    if (tid < NUM_EXPERTS)
        *reinterpret_cast<float*>(smem + BIAS_OFF + tid * 4) = b[tid];
    asm volatile("fence.proxy.async.shared::cta;" ::: "memory");
    __syncthreads();

    if (wid == 16) {
        // ---- TMA producer warp ----
        int s = 0, ep = 1, c = 0, ti = 0;
        for (int g = 0; g < G; g++) {
            if (g >= NSTAGE) mbar_wait(emptyb + s * 8, (uint32_t)ep);
            if (lane == 0) {
                mbar_expect_tx(fullb + s * 8, STAGE_B);
                int tok = (bid + ti * GRID) * TILE_TOK;
                asm volatile(
                    "cp.async.bulk.tensor.2d.shared::cta.global.tile.mbarrier::complete_tx::bytes "
                    "[%0], [%1, {%2, %3}], [%4];"
                    :: "r"(su + X_OFF + s * STAGE_B), "l"(&tmap),
                       "r"(c * KC), "r"(tok), "r"(fullb + s * 8) : "memory");
            }
            if (++s == NSTAGE) { s = 0; ep ^= 1; }
            if (++c == NCH) { c = 0; ti++; }
        }
        return;
    }

    // ---- compute warps: wid = (q<<2) | ks ----
    const int q  = wid >> 2;          // token quarter (32 tokens of 128)
    const int ks = wid & 3;           // K split (8 dims of each 32-dim chunk)
    const uint32_t swz  = (uint32_t)(lane >> 2) << 4;
    const uint32_t d4   = (uint32_t)(ks * 32 + (lane & 3) * 4);
    const uint32_t rowb = (uint32_t)(lane >> 2) * 128 + (uint32_t)q * 4096;
    const uint32_t rA0  = rowb + (d4 ^ swz);
    const uint32_t rA1  = rowb + ((d4 + 16) ^ swz);
    const uint32_t wfl  = su + WF_OFF + (uint32_t)ks * 1024 + (uint32_t)lane * 4;
    const float* b_s = reinterpret_cast<const float*>(smem + BIAS_OFF);

    float acc[16];                    // [m][nt][4]
#pragma unroll
    for (int i = 0; i < 16; i++) acc[i] = 0.0f;

    int s = 0, fp = 0, c = 0, tb = 0;
    for (int g = 0; g < G; g++) {
        mbar_wait(fullb + s * 8, (uint32_t)fp);

        const uint32_t aA = su + X_OFF + (uint32_t)s * STAGE_B + rA0;
        const uint32_t aB = su + X_OFF + (uint32_t)s * STAGE_B + rA1;
        uint32_t a[8];
        asm volatile("ld.shared.b32 %0, [%1];"           : "=r"(a[0]) : "r"(aA));
        asm volatile("ld.shared.b32 %0, [%1+1024];"      : "=r"(a[1]) : "r"(aA));
        asm volatile("ld.shared.b32 %0, [%1];"           : "=r"(a[2]) : "r"(aB));
        asm volatile("ld.shared.b32 %0, [%1+1024];"      : "=r"(a[3]) : "r"(aB));
        asm volatile("ld.shared.b32 %0, [%1+2048];"      : "=r"(a[4]) : "r"(aA));
        asm volatile("ld.shared.b32 %0, [%1+3072];"      : "=r"(a[5]) : "r"(aA));
        asm volatile("ld.shared.b32 %0, [%1+2048];"      : "=r"(a[6]) : "r"(aB));
        asm volatile("ld.shared.b32 %0, [%1+3072];"      : "=r"(a[7]) : "r"(aB));
        if (lane == 0) mbar_arrive(emptyb + s * 8);

        // Split x = hi + lo with a mask (hi is exactly tf32-representable;
        // lo = x - hi is exact; HW truncation of lo adds only ~2^-24 of x).
        uint32_t al[8];
#pragma unroll
        for (int i = 0; i < 8; i++) {
            uint32_t hb = a[i] & 0xFFFFE000u;
            al[i] = __float_as_uint(__uint_as_float(a[i]) - __uint_as_float(hb));
            a[i] = hb;
        }

        const uint32_t wb = wfl + (uint32_t)c * 4096;
        uint32_t bf[8];
        asm volatile("ld.shared.b32 %0, [%1];"      : "=r"(bf[0]) : "r"(wb));
        asm volatile("ld.shared.b32 %0, [%1+128];"  : "=r"(bf[1]) : "r"(wb));
        asm volatile("ld.shared.b32 %0, [%1+256];"  : "=r"(bf[2]) : "r"(wb));
        asm volatile("ld.shared.b32 %0, [%1+384];"  : "=r"(bf[3]) : "r"(wb));
        asm volatile("ld.shared.b32 %0, [%1+512];"  : "=r"(bf[4]) : "r"(wb));
        asm volatile("ld.shared.b32 %0, [%1+640];"  : "=r"(bf[5]) : "r"(wb));
        asm volatile("ld.shared.b32 %0, [%1+768];"  : "=r"(bf[6]) : "r"(wb));
        asm volatile("ld.shared.b32 %0, [%1+896];"  : "=r"(bf[7]) : "r"(wb));

        // term 1: xh * Wh (4 independent accumulators -> ILP)
        mma_tf32(acc + 0,  a + 0, bf + 0);
        mma_tf32(acc + 4,  a + 0, bf + 2);
        mma_tf32(acc + 8,  a + 4, bf + 0);
        mma_tf32(acc + 12, a + 4, bf + 2);
        // term 2: xh * Wl
        mma_tf32(acc + 0,  a + 0, bf + 4);
        mma_tf32(acc + 4,  a + 0, bf + 6);
        mma_tf32(acc + 8,  a + 4, bf + 4);
        mma_tf32(acc + 12, a + 4, bf + 6);
        // term 3: xl * Wh
        mma_tf32(acc + 0,  al + 0, bf + 0);
        mma_tf32(acc + 4,  al + 0, bf + 2);
        mma_tf32(acc + 8,  al + 4, bf + 0);
        mma_tf32(acc + 12, al + 4, bf + 2);

        if (++s == NSTAGE) { s = 0; fp ^= 1; }
        if (++c == NCH) {
            c = 0;
            // ---- per-tile epilogue (single-buffer scratch) ----
            const uint32_t scr = su + SCR_OFF + (uint32_t)ks * SCR_KS;
#pragma unroll
            for (int m = 0; m < 2; m++) {
#pragma unroll
                for (int nt = 0; nt < 2; nt++) {
                    int tokr = q * 32 + m * 16 + (lane >> 2);
                    uint32_t ad = scr + (uint32_t)tokr * 80
                                + (uint32_t)(nt * 8 + (lane & 3) * 2) * 4;
                    const float* A4 = acc + (m * 2 + nt) * 4;
                    asm volatile("st.shared.v2.f32 [%0], {%1, %2};"
                                 :: "r"(ad), "f"(A4[0]), "f"(A4[1]) : "memory");
                    asm volatile("st.shared.v2.f32 [%0+640], {%1, %2};"
                                 :: "r"(ad), "f"(A4[2]), "f"(A4[3]) : "memory");
                }
            }
            asm volatile("bar.sync 1, 512;" ::: "memory");

            if (tid < TILE_TOK) {
                const uint32_t sb = su + SCR_OFF + (uint32_t)tid * 80;
                float lg[16];
#pragma unroll
                for (int i = 0; i < 16; i++) lg[i] = b_s[i];
#pragma unroll
                for (int s4 = 0; s4 < 4; s4++) {
#pragma unroll
                    for (int qd = 0; qd < 4; qd++) {
                        float v0, v1, v2, v3;
                        asm volatile("ld.shared.v4.f32 {%0, %1, %2, %3}, [%4];"
                                     : "=f"(v0), "=f"(v1), "=f"(v2), "=f"(v3)
                                     : "r"(sb + (uint32_t)(s4 * SCR_KS + qd * 16)));
                        lg[qd * 4 + 0] += v0; lg[qd * 4 + 1] += v1;
                        lg[qd * 4 + 2] += v2; lg[qd * 4 + 3] += v3;
                    }
                }
                float m = lg[0];
#pragma unroll
                for (int e = 1; e < NUM_EXPERTS; e++) m = fmaxf(m, lg[e]);
                float sum = 0.0f;
#pragma unroll
                for (int e = 0; e < NUM_EXPERTS; e++) {
                    float w = __expf(lg[e] - m);
                    lg[e] = w;
                    sum += w;
                }
                const float inv = __fdividef(1.0f, sum);
#pragma unroll
                for (int e = 0; e < NUM_EXPERTS; e++) lg[e] *= inv;

                float v1 = -1.0f, v2 = -1.0f;
                int i1 = 0, i2 = 0;
#pragma unroll
                for (int e = 0; e < NUM_EXPERTS; e++) {
                    float w = lg[e];
                    if (w > v1) { v2 = v1; i2 = i1; v1 = w; i1 = e; }
                    else if (w > v2) { v2 = w; i2 = e; }
                }
                const size_t t = (size_t)(bid + tb * GRID) * TILE_TOK + tid;
                float* outg = out;
                float* outw = out + (size_t)NUM_EXPERTS * T;
#pragma unroll
                for (int e = 0; e < NUM_EXPERTS; e++) {
                    float gg = (e == i1) ? v1 : ((e == i2) ? v2 : 0.0f);
                    outg[(size_t)e * T + t] = gg;
                    outw[(size_t)e * T + t] = lg[e];
                }
            }
            asm volatile("bar.sync 1, 512;" ::: "memory");  // scratch reusable
#pragma unroll
            for (int i = 0; i < 16; i++) acc[i] = 0.0f;
            tb++;
        }
    }
}

typedef CUresult (*PFN_encodeTiled)(
    CUtensorMap*, CUtensorMapDataType, cuuint32_t, void*,
    const cuuint64_t*, const cuuint64_t*, const cuuint32_t*, const cuuint32_t*,
    CUtensorMapInterleave, CUtensorMapSwizzle, CUtensorMapL2promotion,
    CUtensorMapFloatOOBfill);

extern "C" void kernel_launch(void* const* d_in, const int* in_sizes, int n_in,
                              void* d_out, int out_size) {
    const float* x = (const float*)d_in[0];
    const float* W = (const float*)d_in[1];
    const float* b = (const float*)d_in[2];
    float* out = (float*)d_out;
    const int T = in_sizes[0] / DIM;           // 65536 tokens

    static PFN_encodeTiled encode_fn = nullptr;
    if (!encode_fn) {
        void* fp = nullptr;
        cudaDriverEntryPointQueryResult st;
        cudaGetDriverEntryPoint("cuTensorMapEncodeTiled", &fp,
                                cudaEnableDefault, &st);
        encode_fn = (PFN_encodeTiled)fp;
    }

    CUtensorMap tmap;
    {
        cuuint64_t gdims[2]    = {(cuuint64_t)DIM, (cuuint64_t)T};
        cuuint64_t gstrides[1] = {(cuuint64_t)DIM * 4};
        cuuint32_t box[2]      = {KC, TILE_TOK};
        cuuint32_t estr[2]     = {1, 1};
        encode_fn(&tmap, CU_TENSOR_MAP_DATA_TYPE_FLOAT32, 2, (void*)x,
                  gdims, gstrides, box, estr,
                  CU_TENSOR_MAP_INTERLEAVE_NONE, CU_TENSOR_MAP_SWIZZLE_128B,
                  CU_TENSOR_MAP_L2_PROMOTION_L2_128B,
                  CU_TENSOR_MAP_FLOAT_OOB_FILL_NONE);
    }

    cudaFuncSetAttribute(gating_kernel,
                         cudaFuncAttributeMaxDynamicSharedMemorySize, SMEM_BYTES);
    gating_kernel<<<GRID, THREADS, SMEM_BYTES>>>(W, b, out, T, tmap);
}

// round 16
// speedup vs baseline: 1.2563x; 1.1540x over previous
#include <cuda_runtime.h>
#include <cuda.h>
#include <cstdint>

#define NUM_EXPERTS 16
#define DIM 1024
#define THREADS 544            // 16 compute warps + 1 producer warp
#define GRID 148
#define TILE_TOK 128
#define KC 32                  // dims per chunk
#define NCH 32                 // chunks per tile
#define NSTAGE 5
#define STAGE_B 16384          // 128 tok x 32 dims x 4B, SW128

// smem layout (bytes)
#define WH_OFF   0             // 64KB W_hi fragments (tf32-masked f32)
#define WL_OFF   65536         // 32KB W_lo fragments (bf16)
#define X_OFF    98304         // 5 x 16KB stages
#define SCR_OFF  (X_OFF + NSTAGE * STAGE_B)      // 180224
#define SCR_KS   10240                           // 128 tok x 80B per ksplit
#define BIAS_OFF (SCR_OFF + 4 * SCR_KS)          // 221184
#define MB_OFF   (BIAS_OFF + 64)                 // full[5]@0, empty[5]@48
#define SMEM_BYTES (MB_OFF + 96 + 32)            // 221376

__device__ __forceinline__ void mbar_init(uint32_t bar, uint32_t cnt) {
    asm volatile("mbarrier.init.shared.b64 [%0], %1;" :: "r"(bar), "r"(cnt) : "memory");
}
__device__ __forceinline__ void mbar_expect_tx(uint32_t bar, uint32_t bytes) {
    asm volatile("mbarrier.arrive.expect_tx.shared.b64 _, [%0], %1;"
                 :: "r"(bar), "r"(bytes) : "memory");
}
__device__ __forceinline__ void mbar_arrive(uint32_t bar) {
    asm volatile("mbarrier.arrive.shared.b64 _, [%0];" :: "r"(bar) : "memory");
}
__device__ __forceinline__ void mbar_wait(uint32_t bar, uint32_t parity) {
    uint32_t done;
    asm volatile(
        "{\n\t.reg .pred p;\n\t"
        "mbarrier.try_wait.parity.acquire.cta.shared::cta.b64 p, [%1], %2;\n\t"
        "selp.b32 %0, 1, 0, p;\n\t}"
        : "=r"(done) : "r"(bar), "r"(parity) : "memory");
    if (!done) {
        asm volatile(
            "{\n\t.reg .pred P1;\n\t"
            "WL_%=:\n\t"
            "mbarrier.try_wait.parity.acquire.cta.shared::cta.b64 P1, [%0], %1, 0x989680;\n\t"
            "@P1 bra.uni WD_%=;\n\t"
            "bra.uni WL_%=;\n\t"
            "WD_%=:\n\t}"
            :: "r"(bar), "r"(parity) : "memory");
    }
}

__device__ __forceinline__ void mma_tf32(float* d, const uint32_t* a, const uint32_t* bf) {
    asm volatile(
        "mma.sync.aligned.m16n8k8.row.col.f32.tf32.tf32.f32 "
        "{%0,%1,%2,%3}, {%4,%5,%6,%7}, {%8,%9}, {%0,%1,%2,%3};"
        : "+f"(d[0]), "+f"(d[1]), "+f"(d[2]), "+f"(d[3])
        : "r"(a[0]), "r"(a[1]), "r"(a[2]), "r"(a[3]), "r"(bf[0]), "r"(bf[1]));
}

__global__ __launch_bounds__(THREADS, 1)
void gating_kernel(const float* __restrict__ W,
                   const float* __restrict__ b,
                   float* __restrict__ out,
                   int T,
                   const __grid_constant__ CUtensorMap tmap) {
    extern __shared__ char smem[];
    const uint32_t su = (uint32_t)__cvta_generic_to_shared(smem);
    const int tid  = threadIdx.x;
    const int wid  = tid >> 5;
    const int lane = tid & 31;
    const int NT   = T / TILE_TOK;                       // 512 tiles
    const int bid  = blockIdx.x;
    const int ntl  = (NT - bid + GRID - 1) / GRID;       // tiles for this CTA
    const int G    = ntl * NCH;

    const uint32_t fullb  = su + MB_OFF;
    const uint32_t emptyb = su + MB_OFF + 48;

    if (tid == 0) {
#pragma unroll
        for (int i = 0; i < NSTAGE; i++) {
            mbar_init(fullb + i * 8, 1);
            mbar_init(emptyb + i * 8, 16);
        }
    }

    // Pack W fragments. Linear index i = ((k2*2+nt)*2+reg)*32 + l.
    // hi = tf32-masked f32 at WH_OFF + i*4; lo = bf16(W - hi) at WL_OFF + i*2.
    // e = nt*8 + (l>>2), d = k2*8 + (l&3) + reg*4.
    for (int i = tid; i < 16384; i += THREADS) {
        int l = i & 31, reg = (i >> 5) & 1, nt = (i >> 6) & 1, k2 = i >> 7;
        int e = nt * 8 + (l >> 2);
        int d = k2 * 8 + (l & 3) + reg * 4;
        float w = W[(e << 10) | d];
        uint32_t hb = __float_as_uint(w) & 0xFFFFE000u;
        float lo = w - __uint_as_float(hb);
        uint32_t lb = __float_as_uint(lo);
        uint32_t rb = (lb + 0x7FFFu + ((lb >> 16) & 1u)) >> 16;   // bf16 rne
        *reinterpret_cast<uint32_t*>(smem + WH_OFF + (size_t)i * 4) = hb;
        *reinterpret_cast<uint16_t*>(smem + WL_OFF + (size_t)i * 2) = (uint16_t)rb;
    }
    if (tid < NUM_EXPERTS)
        *reinterpret_cast<float*>(smem + BIAS_OFF + tid * 4) = b[tid];
    asm volatile("fence.proxy.async.shared::cta;" ::: "memory");
    __syncthreads();

    if (wid == 16) {
        // ---- TMA producer warp ----
        int s = 0, ep = 1, c = 0, ti = 0;
        for (int g = 0; g < G; g++) {
            if (g >= NSTAGE) mbar_wait(emptyb + s * 8, (uint32_t)ep);
            if (lane == 0) {
                mbar_expect_tx(fullb + s * 8, STAGE_B);
                int tok = (bid + ti * GRID) * TILE_TOK;
                asm volatile(
                    "cp.async.bulk.tensor.2d.shared::cta.global.tile.mbarrier::complete_tx::bytes "
                    "[%0], [%1, {%2, %3}], [%4];"
                    :: "r"(su + X_OFF + s * STAGE_B), "l"(&tmap),
                       "r"(c * KC), "r"(tok), "r"(fullb + s * 8) : "memory");
            }
            if (++s == NSTAGE) { s = 0; ep ^= 1; }
            if (++c == NCH) { c = 0; ti++; }
        }
        return;
    }

    // ---- compute warps: wid = (q<<2) | ks ----
    const int q  = wid >> 2;          // token quarter (32 tokens of 128)
    const int ks = wid & 3;           // K split (8 dims of each 32-dim chunk)
    const uint32_t swz  = (uint32_t)(lane >> 2) << 4;
    const uint32_t d4   = (uint32_t)(ks * 32 + (lane & 3) * 4);
    const uint32_t rowb = (uint32_t)(lane >> 2) * 128 + (uint32_t)q * 4096;
    const uint32_t rA0  = rowb + (d4 ^ swz);
    const uint32_t rA1  = rowb + ((d4 + 16) ^ swz);
    const uint32_t whb  = su + WH_OFF + (uint32_t)ks * 512 + (uint32_t)lane * 4;
    const uint32_t wlb  = su + WL_OFF + (uint32_t)ks * 256 + (uint32_t)lane * 2;
    const float* b_s = reinterpret_cast<const float*>(smem + BIAS_OFF);

    float acc[16];                    // [m][nt][4]
#pragma unroll
    for (int i = 0; i < 16; i++) acc[i] = 0.0f;

    int s = 0, fp = 0, c = 0, tb = 0;
    for (int g = 0; g < G; g++) {
        mbar_wait(fullb + s * 8, (uint32_t)fp);

        const uint32_t aA = su + X_OFF + (uint32_t)s * STAGE_B + rA0;
        const uint32_t aB = su + X_OFF + (uint32_t)s * STAGE_B + rA1;
        uint32_t a[8];
        asm volatile("ld.shared.b32 %0, [%1];"           : "=r"(a[0]) : "r"(aA));
        asm volatile("ld.shared.b32 %0, [%1+1024];"      : "=r"(a[1]) : "r"(aA));
        asm volatile("ld.shared.b32 %0, [%1];"           : "=r"(a[2]) : "r"(aB));
        asm volatile("ld.shared.b32 %0, [%1+1024];"      : "=r"(a[3]) : "r"(aB));
        asm volatile("ld.shared.b32 %0, [%1+2048];"      : "=r"(a[4]) : "r"(aA));
        asm volatile("ld.shared.b32 %0, [%1+3072];"      : "=r"(a[5]) : "r"(aA));
        asm volatile("ld.shared.b32 %0, [%1+2048];"      : "=r"(a[6]) : "r"(aB));
        asm volatile("ld.shared.b32 %0, [%1+3072];"      : "=r"(a[7]) : "r"(aB));
        if (lane == 0) mbar_arrive(emptyb + s * 8);

        // Split x = hi + lo with a mask (hi exactly tf32; lo exact in f32).
        uint32_t al[8];
#pragma unroll
        for (int i = 0; i < 8; i++) {
            uint32_t hb = a[i] & 0xFFFFE000u;
            al[i] = __float_as_uint(__uint_as_float(a[i]) - __uint_as_float(hb));
            a[i] = hb;
        }

        // B fragments: hi f32 + lo bf16 (shift to f32 bits; exactly tf32).
        const uint32_t wh = whb + (uint32_t)c * 2048;
        const uint32_t wl = wlb + (uint32_t)c * 1024;
        uint32_t bh[4], bl[4];
        asm volatile("ld.shared.b32 %0, [%1];"      : "=r"(bh[0]) : "r"(wh));
        asm volatile("ld.shared.b32 %0, [%1+128];"  : "=r"(bh[1]) : "r"(wh));
        asm volatile("ld.shared.b32 %0, [%1+256];"  : "=r"(bh[2]) : "r"(wh));
        asm volatile("ld.shared.b32 %0, [%1+384];"  : "=r"(bh[3]) : "r"(wh));
        {
            uint16_t l0, l1, l2, l3;
            asm volatile("ld.shared.u16 %0, [%1];"      : "=h"(l0) : "r"(wl));
            asm volatile("ld.shared.u16 %0, [%1+64];"   : "=h"(l1) : "r"(wl));
            asm volatile("ld.shared.u16 %0, [%1+128];"  : "=h"(l2) : "r"(wl));
            asm volatile("ld.shared.u16 %0, [%1+192];"  : "=h"(l3) : "r"(wl));
            bl[0] = (uint32_t)l0 << 16; bl[1] = (uint32_t)l1 << 16;
            bl[2] = (uint32_t)l2 << 16; bl[3] = (uint32_t)l3 << 16;
        }

        // term 1: xh * Wh (4 independent accumulators -> ILP)
        mma_tf32(acc + 0,  a + 0, bh + 0);
        mma_tf32(acc + 4,  a + 0, bh + 2);
        mma_tf32(acc + 8,  a + 4, bh + 0);
        mma_tf32(acc + 12, a + 4, bh + 2);
        // term 2: xh * Wl
        mma_tf32(acc + 0,  a + 0, bl + 0);
        mma_tf32(acc + 4,  a + 0, bl + 2);
        mma_tf32(acc + 8,  a + 4, bl + 0);
        mma_tf32(acc + 12, a + 4, bl + 2);
        // term 3: xl * Wh
        mma_tf32(acc + 0,  al + 0, bh + 0);
        mma_tf32(acc + 4,  al + 0, bh + 2);
        mma_tf32(acc + 8,  al + 4, bh + 0);
        mma_tf32(acc + 12, al + 4, bh + 2);

        if (++s == NSTAGE) { s = 0; fp ^= 1; }
        if (++c == NCH) {
            c = 0;
            // ---- per-tile epilogue (single-buffer scratch) ----
            const uint32_t scr = su + SCR_OFF + (uint32_t)ks * SCR_KS;
#pragma unroll
            for (int m = 0; m < 2; m++) {
#pragma unroll
                for (int nt = 0; nt < 2; nt++) {
                    int tokr = q * 32 + m * 16 + (lane >> 2);
                    uint32_t ad = scr + (uint32_t)tokr * 80
                                + (uint32_t)(nt * 8 + (lane & 3) * 2) * 4;
                    const float* A4 = acc + (m * 2 + nt) * 4;
                    asm volatile("st.shared.v2.f32 [%0], {%1, %2};"
                                 :: "r"(ad), "f"(A4[0]), "f"(A4[1]) : "memory");
                    asm volatile("st.shared.v2.f32 [%0+640], {%1, %2};"
                                 :: "r"(ad), "f"(A4[2]), "f"(A4[3]) : "memory");
                }
            }
            asm volatile("bar.sync 1, 512;" ::: "memory");

            if (tid < TILE_TOK) {
                const uint32_t sb = su + SCR_OFF + (uint32_t)tid * 80;
                float lg[16];
#pragma unroll
                for (int i = 0; i < 16; i++) lg[i] = b_s[i];
#pragma unroll
                for (int s4 = 0; s4 < 4; s4++) {
#pragma unroll
                    for (int qd = 0; qd < 4; qd++) {
                        float v0, v1, v2, v3;
                        asm volatile("ld.shared.v4.f32 {%0, %1, %2, %3}, [%4];"
                                     : "=f"(v0), "=f"(v1), "=f"(v2), "=f"(v3)
                                     : "r"(sb + (uint32_t)(s4 * SCR_KS + qd * 16)));
                        lg[qd * 4 + 0] += v0; lg[qd * 4 + 1] += v1;
                        lg[qd * 4 + 2] += v2; lg[qd * 4 + 3] += v3;
                    }
                }
                float m = lg[0];
#pragma unroll
                for (int e = 1; e < NUM_EXPERTS; e++) m = fmaxf(m, lg[e]);
                float sum = 0.0f;
#pragma unroll
                for (int e = 0; e < NUM_EXPERTS; e++) {
                    float w = __expf(lg[e] - m);
                    lg[e] = w;
                    sum += w;
                }
                const float inv = __fdividef(1.0f, sum);
#pragma unroll
                for (int e = 0; e < NUM_EXPERTS; e++) lg[e] *= inv;

                float v1 = -1.0f, v2 = -1.0f;
                int i1 = 0, i2 = 0;
#pragma unroll
                for (int e = 0; e < NUM_EXPERTS; e++) {
                    float w = lg[e];
                    if (w > v1) { v2 = v1; i2 = i1; v1 = w; i1 = e; }
                    else if (w > v2) { v2 = w; i2 = e; }
                }
                const size_t t = (size_t)(bid + tb * GRID) * TILE_TOK + tid;
                float* outg = out;
                float* outw = out + (size_t)NUM_EXPERTS * T;
#pragma unroll
                for (int e = 0; e < NUM_EXPERTS; e++) {
                    float gg = (e == i1) ? v1 : ((e == i2) ? v2 : 0.0f);
                    outg[(size_t)e * T + t] = gg;
                    outw[(size_t)e * T + t] = lg[e];
                }
            }
            asm volatile("bar.sync 1, 512;" ::: "memory");  // scratch reusable
#pragma unroll
            for (int i = 0; i < 16; i++) acc[i] = 0.0f;
            tb++;
        }
    }
}

typedef CUresult (*PFN_encodeTiled)(
    CUtensorMap*, CUtensorMapDataType, cuuint32_t, void*,
    const cuuint64_t*, const cuuint64_t*, const cuuint32_t*, const cuuint32_t*,
    CUtensorMapInterleave, CUtensorMapSwizzle, CUtensorMapL2promotion,
    CUtensorMapFloatOOBfill);

extern "C" void kernel_launch(void* const* d_in, const int* in_sizes, int n_in,
                              void* d_out, int out_size) {
    const float* x = (const float*)d_in[0];
    const float* W = (const float*)d_in[1];
    const float* b = (const float*)d_in[2];
    float* out = (float*)d_out;
    const int T = in_sizes[0] / DIM;           // 65536 tokens

    static PFN_encodeTiled encode_fn = nullptr;
    if (!encode_fn) {
        void* fp = nullptr;
        cudaDriverEntryPointQueryResult st;
        cudaGetDriverEntryPoint("cuTensorMapEncodeTiled", &fp,
                                cudaEnableDefault, &st);
        encode_fn = (PFN_encodeTiled)fp;
    }

    CUtensorMap tmap;
    {
        cuuint64_t gdims[2]    = {(cuuint64_t)DIM, (cuuint64_t)T};
        cuuint64_t gstrides[1] = {(cuuint64_t)DIM * 4};
        cuuint32_t box[2]      = {KC, TILE_TOK};
        cuuint32_t estr[2]     = {1, 1};
        encode_fn(&tmap, CU_TENSOR_MAP_DATA_TYPE_FLOAT32, 2, (void*)x,
                  gdims, gstrides, box, estr,
                  CU_TENSOR_MAP_INTERLEAVE_NONE, CU_TENSOR_MAP_SWIZZLE_128B,
                  CU_TENSOR_MAP_L2_PROMOTION_L2_256B,
                  CU_TENSOR_MAP_FLOAT_OOB_FILL_NONE);
    }

    cudaFuncSetAttribute(gating_kernel,
                         cudaFuncAttributeMaxDynamicSharedMemorySize, SMEM_BYTES);
    gating_kernel<<<GRID, THREADS, SMEM_BYTES>>>(W, b, out, T, tmap);
}